// round 5
// baseline (speedup 1.0000x reference)
#include <cuda_runtime.h>

// 5x5 box-filter mean, reflect padding, NCHW fp32, H=W=512.
// smem-free, VERTICAL-FIRST separable filter:
//   8 front-batched LDG.128 per thread -> vertical 5-sums (no cross-lane)
//   -> horizontal 5-tap on the 4 summed rows via 4 shuffles/row
//   (lanes 0/31 substitute vertically-summed reflect halo columns)
//   -> 4x STG.128.

#define IMG 512
#define TW  128   // tile width  (floats) = 32 lanes * 4
#define TH  32    // tile height (rows)   = 8 warps * 4

__device__ __forceinline__ int refl(int x) {
    return (x < 0) ? -x : ((x >= IMG) ? (2 * IMG - 2 - x) : x);
}

__global__ __launch_bounds__(256, 5)
void box5_kernel(const float* __restrict__ in, float* __restrict__ out)
{
    const int lane = threadIdx.x;       // 0..31 -> float4 column
    const int wrp  = threadIdx.y;       // 0..7  -> 4-row group

    const int tile_x = blockIdx.x * TW;
    const int tile_y = blockIdx.y * TH;
    const float* __restrict__ img  = in  + (size_t)blockIdx.z * (IMG * IMG);
    float* __restrict__       oimg = out + (size_t)blockIdx.z * (IMG * IMG);

    const int colx  = tile_x + lane * 4;
    const int rbase = tile_y + wrp * 4 - 2;   // first of 8 input rows

    // ---- Front-batched loads: 8 rows x LDG.128 ----
    int gy[8];
    #pragma unroll
    for (int k = 0; k < 8; k++) gy[k] = refl(rbase + k);

    float4 c[8];
    #pragma unroll
    for (int k = 0; k < 8; k++)
        c[k] = *reinterpret_cast<const float4*>(img + gy[k] * IMG + colx);

    // ---- x-halo: lanes 0/31 load 2 reflected scalar columns (8 rows) ----
    float e0[8], e1[8];
    if (lane == 0) {
        const int xl0 = refl(tile_x - 2), xl1 = refl(tile_x - 1);
        #pragma unroll
        for (int k = 0; k < 8; k++) {
            e0[k] = img[gy[k] * IMG + xl0];
            e1[k] = img[gy[k] * IMG + xl1];
        }
    } else if (lane == 31) {
        const int xr0 = refl(tile_x + TW), xr1 = refl(tile_x + TW + 1);
        #pragma unroll
        for (int k = 0; k < 8; k++) {
            e0[k] = img[gy[k] * IMG + xr0];
            e1[k] = img[gy[k] * IMG + xr1];
        }
    }

    // ---- Vertical 5-sums (running window): 4 output rows ----
    float4 v[4];
    v[0].x = c[0].x + c[1].x + c[2].x + c[3].x + c[4].x;
    v[0].y = c[0].y + c[1].y + c[2].y + c[3].y + c[4].y;
    v[0].z = c[0].z + c[1].z + c[2].z + c[3].z + c[4].z;
    v[0].w = c[0].w + c[1].w + c[2].w + c[3].w + c[4].w;
    #pragma unroll
    for (int r = 1; r < 4; r++) {
        v[r].x = v[r-1].x - c[r-1].x + c[r+4].x;
        v[r].y = v[r-1].y - c[r-1].y + c[r+4].y;
        v[r].z = v[r-1].z - c[r-1].z + c[r+4].z;
        v[r].w = v[r-1].w - c[r-1].w + c[r+4].w;
    }

    // Vertical sums of the halo columns (only meaningful on lanes 0/31)
    float ve0[4], ve1[4];
    ve0[0] = e0[0] + e0[1] + e0[2] + e0[3] + e0[4];
    ve1[0] = e1[0] + e1[1] + e1[2] + e1[3] + e1[4];
    #pragma unroll
    for (int r = 1; r < 4; r++) {
        ve0[r] = ve0[r-1] - e0[r-1] + e0[r+4];
        ve1[r] = ve1[r-1] - e1[r-1] + e1[r+4];
    }

    // ---- Horizontal 5-tap on vertically-summed rows + scale + store ----
    const float inv25 = 1.0f / 25.0f;
    float* obase = oimg + (tile_y + wrp * 4) * IMG + colx;

    #pragma unroll
    for (int r = 0; r < 4; r++) {
        float pz = __shfl_up_sync(0xffffffffu, v[r].z, 1);   // col -2
        float pw = __shfl_up_sync(0xffffffffu, v[r].w, 1);   // col -1
        float nx = __shfl_down_sync(0xffffffffu, v[r].x, 1); // col +4
        float ny = __shfl_down_sync(0xffffffffu, v[r].y, 1); // col +5
        if (lane == 0)  { pz = ve0[r]; pw = ve1[r]; }
        if (lane == 31) { nx = ve0[r]; ny = ve1[r]; }

        const float s = v[r].x + v[r].y + v[r].z + v[r].w;
        float4 o;
        o.x = ((s - v[r].w) + pz + pw) * inv25;   // cols -2..2
        o.y = (s + pw) * inv25;                   // cols -1..3
        o.z = (s + nx) * inv25;                   // cols  0..4
        o.w = ((s - v[r].x) + nx + ny) * inv25;   // cols  1..5
        *reinterpret_cast<float4*>(obase + r * IMG) = o;
    }
}

extern "C" void kernel_launch(void* const* d_in, const int* in_sizes, int n_in,
                              void* d_out, int out_size)
{
    const float* in = (const float*)d_in[0];
    float* out = (float*)d_out;

    const int planes = in_sizes[0] / (IMG * IMG);   // 96

    dim3 grid(IMG / TW, IMG / TH, planes);          // (4, 16, 96)
    dim3 block(32, 8);
    box5_kernel<<<grid, block>>>(in, out);
}

// round 7
// speedup vs baseline: 1.1535x; 1.1535x over previous
#include <cuda_runtime.h>

// 5x5 box-filter mean, reflect padding, NCHW fp32, H=W=512.
// smem-free, horizontal-first separable filter (best-ILP dataflow):
//   8 front-batched LDG.128/thread -> per-row horizontal 5-sum via 4 shuffles
//   (lanes 0/31 substitute the reflect halo: aligned float2 on interior tiles,
//   scalar loads on the two boundary tiles) -> shared-partial vertical 5-sums
//   -> 4x STG.128.

#define IMG 512
#define TW  128   // tile width  (floats) = 32 lanes * 4
#define TH  32    // tile height (rows)   = 8 warps * 4

__device__ __forceinline__ int refl(int x) {
    return (x < 0) ? -x : ((x >= IMG) ? (2 * IMG - 2 - x) : x);
}

__global__ __launch_bounds__(256, 5)
void box5_kernel(const float* __restrict__ in, float* __restrict__ out)
{
    const int lane = threadIdx.x;       // 0..31 -> float4 column
    const int wrp  = threadIdx.y;       // 0..7  -> 4-row group

    const int tile_x = blockIdx.x * TW;
    const int tile_y = blockIdx.y * TH;
    const float* __restrict__ img  = in  + (size_t)blockIdx.z * (IMG * IMG);
    float* __restrict__       oimg = out + (size_t)blockIdx.z * (IMG * IMG);

    const int colx  = tile_x + lane * 4;
    const int rbase = tile_y + wrp * 4 - 2;   // first of 8 input rows

    // ---- Front-batched loads: 8 rows x LDG.128 ----
    int gy[8];
    #pragma unroll
    for (int k = 0; k < 8; k++) gy[k] = refl(rbase + k);

    float4 c[8];
    #pragma unroll
    for (int k = 0; k < 8; k++)
        c[k] = *reinterpret_cast<const float4*>(img + gy[k] * IMG + colx);

    // ---- x-halo for lanes 0/31: e[k].x = col -2 (resp +4), e[k].y = col -1 (resp +5) ----
    float2 e[8];
    if (lane == 0) {
        if (tile_x == 0) {
            // reflect: col -2 -> 2, col -1 -> 1  (odd offsets: scalar loads)
            #pragma unroll
            for (int k = 0; k < 8; k++) {
                const float* rp = img + gy[k] * IMG;
                e[k].x = rp[2];
                e[k].y = rp[1];
            }
        } else {
            // cols tile_x-2, tile_x-1 : tile_x-2 is even -> 8B aligned
            #pragma unroll
            for (int k = 0; k < 8; k++)
                e[k] = *reinterpret_cast<const float2*>(img + gy[k] * IMG + tile_x - 2);
        }
    } else if (lane == 31) {
        if (tile_x + TW == IMG) {
            // reflect: col 512 -> 510, col 513 -> 509 (odd offsets: scalar loads)
            #pragma unroll
            for (int k = 0; k < 8; k++) {
                const float* rp = img + gy[k] * IMG;
                e[k].x = rp[IMG - 2];
                e[k].y = rp[IMG - 3];
            }
        } else {
            // cols tile_x+128, tile_x+129 : even offset -> 8B aligned
            #pragma unroll
            for (int k = 0; k < 8; k++)
                e[k] = *reinterpret_cast<const float2*>(img + gy[k] * IMG + tile_x + TW);
        }
    }

    // ---- Horizontal 5-sums via shuffles (independent per row: high ILP) ----
    float4 h[8];
    #pragma unroll
    for (int k = 0; k < 8; k++) {
        float pz = __shfl_up_sync(0xffffffffu, c[k].z, 1);   // col -2
        float pw = __shfl_up_sync(0xffffffffu, c[k].w, 1);   // col -1
        float nx = __shfl_down_sync(0xffffffffu, c[k].x, 1); // col +4
        float ny = __shfl_down_sync(0xffffffffu, c[k].y, 1); // col +5
        if (lane == 0)  { pz = e[k].x; pw = e[k].y; }
        if (lane == 31) { nx = e[k].x; ny = e[k].y; }

        const float s = c[k].x + c[k].y + c[k].z + c[k].w;
        h[k].x = (s - c[k].w) + pz + pw;   // cols -2..2
        h[k].y = s + pw;                   // cols -1..3
        h[k].z = s + nx;                   // cols  0..4
        h[k].w = (s - c[k].x) + nx + ny;   // cols  1..5
    }

    // ---- Vertical 5-sums with shared partials + scale + 4x STG.128 ----
    //   A = h1+h2, B = h3+h4, C = h5+h6
    //   v0 = h0+A+B ; v1 = A+B+h5 ; v2 = h2+B+C ; v3 = B+C+h7
    const float inv25 = 1.0f / 25.0f;
    float* obase = oimg + (tile_y + wrp * 4) * IMG + colx;

    float4 A, B, C;
    A.x = h[1].x + h[2].x;  A.y = h[1].y + h[2].y;  A.z = h[1].z + h[2].z;  A.w = h[1].w + h[2].w;
    B.x = h[3].x + h[4].x;  B.y = h[3].y + h[4].y;  B.z = h[3].z + h[4].z;  B.w = h[3].w + h[4].w;
    C.x = h[5].x + h[6].x;  C.y = h[5].y + h[6].y;  C.z = h[5].z + h[6].z;  C.w = h[5].w + h[6].w;

    float4 o;
    o.x = (h[0].x + A.x + B.x) * inv25;
    o.y = (h[0].y + A.y + B.y) * inv25;
    o.z = (h[0].z + A.z + B.z) * inv25;
    o.w = (h[0].w + A.w + B.w) * inv25;
    *reinterpret_cast<float4*>(obase + 0 * IMG) = o;

    o.x = (A.x + B.x + h[5].x) * inv25;
    o.y = (A.y + B.y + h[5].y) * inv25;
    o.z = (A.z + B.z + h[5].z) * inv25;
    o.w = (A.w + B.w + h[5].w) * inv25;
    *reinterpret_cast<float4*>(obase + 1 * IMG) = o;

    o.x = (h[2].x + B.x + C.x) * inv25;
    o.y = (h[2].y + B.y + C.y) * inv25;
    o.z = (h[2].z + B.z + C.z) * inv25;
    o.w = (h[2].w + B.w + C.w) * inv25;
    *reinterpret_cast<float4*>(obase + 2 * IMG) = o;

    o.x = (B.x + C.x + h[7].x) * inv25;
    o.y = (B.y + C.y + h[7].y) * inv25;
    o.z = (B.z + C.z + h[7].z) * inv25;
    o.w = (B.w + C.w + h[7].w) * inv25;
    *reinterpret_cast<float4*>(obase + 3 * IMG) = o;
}

extern "C" void kernel_launch(void* const* d_in, const int* in_sizes, int n_in,
                              void* d_out, int out_size)
{
    const float* in = (const float*)d_in[0];
    float* out = (float*)d_out;

    const int planes = in_sizes[0] / (IMG * IMG);   // 96

    dim3 grid(IMG / TW, IMG / TH, planes);          // (4, 16, 96)
    dim3 block(32, 8);
    box5_kernel<<<grid, block>>>(in, out);
}

// round 8
// speedup vs baseline: 1.2066x; 1.0460x over previous
#include <cuda_runtime.h>

// 5x5 box-filter mean, reflect padding, NCHW fp32, H=W=512.
// smem-free, VERTICAL-FIRST with TREE partials (high ILP, minimal instrs):
//   8 front-batched LDG.128/thread -> tree vertical 5-sums (no cross-lane,
//   depth ~3) -> horizontal 5-tap on the 4 summed rows via 4 shuffles/row
//   (lanes 0/31 substitute tree-summed reflect halo) -> 4x STG.128.
// No launch_bounds occupancy cap: keep regs ~64 so ptxas front-batches all
// 8 LDG.128 (MLP was the R4 win; reg caps killed it in R5/R7).

#define IMG 512
#define TW  128   // tile width  (floats) = 32 lanes * 4
#define TH  32    // tile height (rows)   = 8 warps * 4

__device__ __forceinline__ int refl(int x) {
    return (x < 0) ? -x : ((x >= IMG) ? (2 * IMG - 2 - x) : x);
}

__global__ __launch_bounds__(256)
void box5_kernel(const float* __restrict__ in, float* __restrict__ out)
{
    const int lane = threadIdx.x;       // 0..31 -> float4 column
    const int wrp  = threadIdx.y;       // 0..7  -> 4-row group

    const int tile_x = blockIdx.x * TW;
    const int tile_y = blockIdx.y * TH;
    const float* __restrict__ img  = in  + (size_t)blockIdx.z * (IMG * IMG);
    float* __restrict__       oimg = out + (size_t)blockIdx.z * (IMG * IMG);

    const int colx  = tile_x + lane * 4;
    const int rbase = tile_y + wrp * 4 - 2;   // first of 8 input rows

    // ---- Front-batched loads: 8 rows x LDG.128 ----
    int gy[8];
    #pragma unroll
    for (int k = 0; k < 8; k++) gy[k] = refl(rbase + k);

    float4 c[8];
    #pragma unroll
    for (int k = 0; k < 8; k++)
        c[k] = *reinterpret_cast<const float4*>(img + gy[k] * IMG + colx);

    // ---- x-halo for lanes 0/31 (e.x = col -2 / +4 ; e.y = col -1 / +5) ----
    float2 e[8];
    #pragma unroll
    for (int k = 0; k < 8; k++) { e[k].x = 0.f; e[k].y = 0.f; }
    if (lane == 0) {
        if (tile_x == 0) {
            #pragma unroll
            for (int k = 0; k < 8; k++) {          // reflect: -2 -> 2, -1 -> 1
                const float* rp = img + gy[k] * IMG;
                e[k].x = rp[2];
                e[k].y = rp[1];
            }
        } else {
            #pragma unroll
            for (int k = 0; k < 8; k++)            // even offset -> aligned LDG.64
                e[k] = *reinterpret_cast<const float2*>(img + gy[k] * IMG + tile_x - 2);
        }
    } else if (lane == 31) {
        if (tile_x + TW == IMG) {
            #pragma unroll
            for (int k = 0; k < 8; k++) {          // reflect: 512 -> 510, 513 -> 509
                const float* rp = img + gy[k] * IMG;
                e[k].x = rp[IMG - 2];
                e[k].y = rp[IMG - 3];
            }
        } else {
            #pragma unroll
            for (int k = 0; k < 8; k++)            // even offset -> aligned LDG.64
                e[k] = *reinterpret_cast<const float2*>(img + gy[k] * IMG + tile_x + TW);
        }
    }

    // ---- Vertical 5-sums via tree partials (independent, depth ~3) ----
    //   a = c1+c2, b = c3+c4, d = c5+c6
    //   v0 = c0+a+b ; v1 = a+b+c5 ; v2 = c2+b+d ; v3 = b+d+c7
    float4 a, b, d;
    a.x = c[1].x + c[2].x;  a.y = c[1].y + c[2].y;  a.z = c[1].z + c[2].z;  a.w = c[1].w + c[2].w;
    b.x = c[3].x + c[4].x;  b.y = c[3].y + c[4].y;  b.z = c[3].z + c[4].z;  b.w = c[3].w + c[4].w;
    d.x = c[5].x + c[6].x;  d.y = c[5].y + c[6].y;  d.z = c[5].z + c[6].z;  d.w = c[5].w + c[6].w;

    float4 v[4];
    v[0].x = c[0].x + a.x + b.x;  v[0].y = c[0].y + a.y + b.y;
    v[0].z = c[0].z + a.z + b.z;  v[0].w = c[0].w + a.w + b.w;
    v[1].x = a.x + b.x + c[5].x;  v[1].y = a.y + b.y + c[5].y;
    v[1].z = a.z + b.z + c[5].z;  v[1].w = a.w + b.w + c[5].w;
    v[2].x = c[2].x + b.x + d.x;  v[2].y = c[2].y + b.y + d.y;
    v[2].z = c[2].z + b.z + d.z;  v[2].w = c[2].w + b.w + d.w;
    v[3].x = b.x + d.x + c[7].x;  v[3].y = b.y + d.y + c[7].y;
    v[3].z = b.z + d.z + c[7].z;  v[3].w = b.w + d.w + c[7].w;

    // Halo columns: same tree (values only meaningful on lanes 0/31)
    float2 ae, be, de, ve[4];
    ae.x = e[1].x + e[2].x;  ae.y = e[1].y + e[2].y;
    be.x = e[3].x + e[4].x;  be.y = e[3].y + e[4].y;
    de.x = e[5].x + e[6].x;  de.y = e[5].y + e[6].y;
    ve[0].x = e[0].x + ae.x + be.x;  ve[0].y = e[0].y + ae.y + be.y;
    ve[1].x = ae.x + be.x + e[5].x;  ve[1].y = ae.y + be.y + e[5].y;
    ve[2].x = e[2].x + be.x + de.x;  ve[2].y = e[2].y + be.y + de.y;
    ve[3].x = be.x + de.x + e[7].x;  ve[3].y = be.y + de.y + e[7].y;

    // ---- Horizontal 5-tap on summed rows (4 shuffles/row) + store ----
    const float inv25 = 1.0f / 25.0f;
    float* obase = oimg + (tile_y + wrp * 4) * IMG + colx;

    #pragma unroll
    for (int r = 0; r < 4; r++) {
        float pz = __shfl_up_sync(0xffffffffu, v[r].z, 1);   // col -2
        float pw = __shfl_up_sync(0xffffffffu, v[r].w, 1);   // col -1
        float nx = __shfl_down_sync(0xffffffffu, v[r].x, 1); // col +4
        float ny = __shfl_down_sync(0xffffffffu, v[r].y, 1); // col +5
        if (lane == 0)  { pz = ve[r].x; pw = ve[r].y; }
        if (lane == 31) { nx = ve[r].x; ny = ve[r].y; }

        const float s = v[r].x + v[r].y + v[r].z + v[r].w;
        float4 o;
        o.x = ((s - v[r].w) + pz + pw) * inv25;   // cols -2..2
        o.y = (s + pw) * inv25;                   // cols -1..3
        o.z = (s + nx) * inv25;                   // cols  0..4
        o.w = ((s - v[r].x) + nx + ny) * inv25;   // cols  1..5
        *reinterpret_cast<float4*>(obase + r * IMG) = o;
    }
}

extern "C" void kernel_launch(void* const* d_in, const int* in_sizes, int n_in,
                              void* d_out, int out_size)
{
    const float* in = (const float*)d_in[0];
    float* out = (float*)d_out;

    const int planes = in_sizes[0] / (IMG * IMG);   // 96

    dim3 grid(IMG / TW, IMG / TH, planes);          // (4, 16, 96)
    dim3 block(32, 8);
    box5_kernel<<<grid, block>>>(in, out);
}

// round 9
// speedup vs baseline: 1.2811x; 1.0617x over previous
#include <cuda_runtime.h>

// 5x5 box-filter mean, reflect padding, NCHW fp32, H=W=512.
// smem-free, vertical-first tree partials + shuffle horizontal (R8 dataflow),
// with register diet:
//   - halo loads DEFERRED until after vertical sums (c[] dead -> lower peak regs;
//     halo rows are L1 hits by then)
//   - interior-y fast path: one base pointer + immediate offsets (no gy[] array)
//   - __launch_bounds__(256, 4): 64-reg cap -> 4 CTAs/SM

#define IMG 512
#define TW  128   // tile width  (floats) = 32 lanes * 4
#define TH  32    // tile height (rows)   = 8 warps * 4

__device__ __forceinline__ int refl(int x) {
    return (x < 0) ? -x : ((x >= IMG) ? (2 * IMG - 2 - x) : x);
}

__global__ __launch_bounds__(256, 4)
void box5_kernel(const float* __restrict__ in, float* __restrict__ out)
{
    const int lane = threadIdx.x;       // 0..31 -> float4 column
    const int wrp  = threadIdx.y;       // 0..7  -> 4-row group

    const int tile_x = blockIdx.x * TW;
    const int tile_y = blockIdx.y * TH;
    const float* __restrict__ img  = in  + (size_t)blockIdx.z * (IMG * IMG);
    float* __restrict__       oimg = out + (size_t)blockIdx.z * (IMG * IMG);

    const int colx  = tile_x + lane * 4;
    const int rbase = tile_y + wrp * 4 - 2;   // first of 8 input rows

    const bool interior_y = (rbase >= 0) && (rbase + 7 < IMG);

    // ---- Front-batched loads: 8 rows x LDG.128 ----
    float4 c[8];
    if (interior_y) {
        const float* p = img + rbase * IMG + colx;
        #pragma unroll
        for (int k = 0; k < 8; k++)
            c[k] = *reinterpret_cast<const float4*>(p + k * IMG);  // imm offsets
    } else {
        #pragma unroll
        for (int k = 0; k < 8; k++)
            c[k] = *reinterpret_cast<const float4*>(img + refl(rbase + k) * IMG + colx);
    }

    // ---- Vertical 5-sums via tree partials (c[] dies here) ----
    //   a = c1+c2, b = c3+c4, d = c5+c6
    //   v0 = c0+a+b ; v1 = a+b+c5 ; v2 = c2+b+d ; v3 = b+d+c7
    float4 a, b, d;
    a.x = c[1].x + c[2].x;  a.y = c[1].y + c[2].y;  a.z = c[1].z + c[2].z;  a.w = c[1].w + c[2].w;
    b.x = c[3].x + c[4].x;  b.y = c[3].y + c[4].y;  b.z = c[3].z + c[4].z;  b.w = c[3].w + c[4].w;
    d.x = c[5].x + c[6].x;  d.y = c[5].y + c[6].y;  d.z = c[5].z + c[6].z;  d.w = c[5].w + c[6].w;

    float4 v[4];
    v[0].x = c[0].x + a.x + b.x;  v[0].y = c[0].y + a.y + b.y;
    v[0].z = c[0].z + a.z + b.z;  v[0].w = c[0].w + a.w + b.w;
    v[1].x = a.x + b.x + c[5].x;  v[1].y = a.y + b.y + c[5].y;
    v[1].z = a.z + b.z + c[5].z;  v[1].w = a.w + b.w + c[5].w;
    v[2].x = c[2].x + b.x + d.x;  v[2].y = c[2].y + b.y + d.y;
    v[2].z = c[2].z + b.z + d.z;  v[2].w = c[2].w + b.w + d.w;
    v[3].x = b.x + d.x + c[7].x;  v[3].y = b.y + d.y + c[7].y;
    v[3].z = b.z + d.z + c[7].z;  v[3].w = b.w + d.w + c[7].w;

    // ---- Deferred x-halo (L1 hits) for lanes 0/31, then vertical tree ----
    float2 ve[4] = {};
    if (lane == 0 || lane == 31) {
        const bool left = (lane == 0);
        // halo source columns (e.x = col -2 / +4 ; e.y = col -1 / +5)
        float2 e[8];
        if (left) {
            if (tile_x == 0) {
                #pragma unroll
                for (int k = 0; k < 8; k++) {          // reflect: -2 -> 2, -1 -> 1
                    const float* rp = img + refl(rbase + k) * IMG;
                    e[k].x = rp[2];
                    e[k].y = rp[1];
                }
            } else {
                #pragma unroll
                for (int k = 0; k < 8; k++)            // even offset -> aligned LDG.64
                    e[k] = *reinterpret_cast<const float2*>(
                        img + refl(rbase + k) * IMG + tile_x - 2);
            }
        } else {
            if (tile_x + TW == IMG) {
                #pragma unroll
                for (int k = 0; k < 8; k++) {          // reflect: 512 -> 510, 513 -> 509
                    const float* rp = img + refl(rbase + k) * IMG;
                    e[k].x = rp[IMG - 2];
                    e[k].y = rp[IMG - 3];
                }
            } else {
                #pragma unroll
                for (int k = 0; k < 8; k++)            // even offset -> aligned LDG.64
                    e[k] = *reinterpret_cast<const float2*>(
                        img + refl(rbase + k) * IMG + tile_x + TW);
            }
        }
        float2 ae, be, de;
        ae.x = e[1].x + e[2].x;  ae.y = e[1].y + e[2].y;
        be.x = e[3].x + e[4].x;  be.y = e[3].y + e[4].y;
        de.x = e[5].x + e[6].x;  de.y = e[5].y + e[6].y;
        ve[0].x = e[0].x + ae.x + be.x;  ve[0].y = e[0].y + ae.y + be.y;
        ve[1].x = ae.x + be.x + e[5].x;  ve[1].y = ae.y + be.y + e[5].y;
        ve[2].x = e[2].x + be.x + de.x;  ve[2].y = e[2].y + be.y + de.y;
        ve[3].x = be.x + de.x + e[7].x;  ve[3].y = be.y + de.y + e[7].y;
    }

    // ---- Horizontal 5-tap on summed rows (4 shuffles/row) + store ----
    const float inv25 = 1.0f / 25.0f;
    float* obase = oimg + (tile_y + wrp * 4) * IMG + colx;

    #pragma unroll
    for (int r = 0; r < 4; r++) {
        float pz = __shfl_up_sync(0xffffffffu, v[r].z, 1);   // col -2
        float pw = __shfl_up_sync(0xffffffffu, v[r].w, 1);   // col -1
        float nx = __shfl_down_sync(0xffffffffu, v[r].x, 1); // col +4
        float ny = __shfl_down_sync(0xffffffffu, v[r].y, 1); // col +5
        if (lane == 0)  { pz = ve[r].x; pw = ve[r].y; }
        if (lane == 31) { nx = ve[r].x; ny = ve[r].y; }

        const float s = v[r].x + v[r].y + v[r].z + v[r].w;
        float4 o;
        o.x = ((s - v[r].w) + pz + pw) * inv25;   // cols -2..2
        o.y = (s + pw) * inv25;                   // cols -1..3
        o.z = (s + nx) * inv25;                   // cols  0..4
        o.w = ((s - v[r].x) + nx + ny) * inv25;   // cols  1..5
        *reinterpret_cast<float4*>(obase + r * IMG) = o;
    }
}

extern "C" void kernel_launch(void* const* d_in, const int* in_sizes, int n_in,
                              void* d_out, int out_size)
{
    const float* in = (const float*)d_in[0];
    float* out = (float*)d_out;

    const int planes = in_sizes[0] / (IMG * IMG);   // 96

    dim3 grid(IMG / TW, IMG / TH, planes);          // (4, 16, 96)
    dim3 block(32, 8);
    box5_kernel<<<grid, block>>>(in, out);
}